// round 13
// baseline (speedup 1.0000x reference)
#include <cuda_runtime.h>

#define Bz 4
#define Cc 256
#define Cii 128
#define Nn 4096
#define KSsplit 16
#define KPB (Nn / KSsplit)   // 256 K per split block

typedef unsigned long long u64;

__device__ __forceinline__ u64 pack2(float lo, float hi) {
    u64 r; asm("mov.b64 %0, {%1,%2};" : "=l"(r) : "f"(lo), "f"(hi)); return r;
}
__device__ __forceinline__ float2 unpack2(u64 v) {
    float2 f; asm("mov.b64 {%0,%1}, %2;" : "=f"(f.x), "=f"(f.y) : "l"(v)); return f;
}
__device__ __forceinline__ u64 fma2(u64 a, u64 b, u64 c) {
    u64 d; asm("fma.rn.f32x2 %0, %1, %2, %3;" : "=l"(d) : "l"(a), "l"(b), "l"(c)); return d;
}

// ---------------- scratch (static device globals; no allocation) -------------
__device__ float g_R[Bz * Cc * Cc];                 // R = B B^T (atomics)
__device__ float g_s[Bz * Cc];                      // row sums of b image (atomics)
__device__ float g_gs[Bz * Cii];                    // g_w @ s
__device__ float g_ps2[Bz * Cii];                   // phi_w @ s + N*phi_b
__device__ float g_U[Bz * Cii * Cc];                // g_w @ R
__device__ float g_S[Bz * Cii * Cii];               // U @ phi_w^T + rank1
__device__ float g_T[Bz * Cc * Cii];                // W_w @ S / N
__device__ float g_Q[Bz * Cc * Cc];                 // T @ theta_w
__device__ float g_dp[Bz * Cc];                     // folded bias (BN included)
__device__ float g_alpha[Cc];                       // BN scale

// ---------------- 128x128 tile geometry ---------------------------------------
#define PAD 132
#define TBUF (32 * PAD)
#define SMEM_BIG (4 * TBUF * 4)   // two tiles, double buffered: 67584 B

// ---------------- zero the atomic-reduce targets ------------------------------
__global__ __launch_bounds__(256) void k_zero() {
    int i = blockIdx.x * 256 + threadIdx.x;
    ((float4*)g_R)[i] = make_float4(0.f, 0.f, 0.f, 0.f);
    if (i < (Bz * Cc) / 4) ((float4*)g_s)[i] = make_float4(0.f, 0.f, 0.f, 0.f);
}

// ---------------- gs = g_w @ s ; ps2 = phi_w @ s + N*phi_b -------------------
__global__ __launch_bounds__(256) void k_gsps(const float* __restrict__ gw,
                                              const float* __restrict__ phiw,
                                              const float* __restrict__ phib) {
    int b = blockIdx.x;
    int tid = threadIdx.x;
    __shared__ float ssh[Cc];
    ssh[tid] = g_s[b * Cc + tid];
    __syncthreads();
    if (tid < Cii) {
        float acc = 0.f;
        for (int c = 0; c < Cc; c++) acc += gw[tid * Cc + c] * ssh[c];
        g_gs[b * Cii + tid] = acc;
    } else {
        int i = tid - Cii;
        float acc = 0.f;
        for (int c = 0; c < Cc; c++) acc += phiw[i * Cc + c] * ssh[c];
        g_ps2[b * Cii + i] = acc + (float)Nn * phib[i];
    }
}

// ---------------- 128x128 micro kernel (verified in R7) ------------------------
__device__ __forceinline__ void mm128(const float* __restrict__ As,
                                      const float* __restrict__ Bs,
                                      int rbase, int cbase, u64 acc[8][4]) {
    #pragma unroll 8
    for (int k = 0; k < 32; k++) {
        const float* ap = &As[k * PAD + rbase];
        const float* bp = &Bs[k * PAD + cbase];
        float4 a0 = *(const float4*)ap;
        float4 a1 = *(const float4*)(ap + 4);
        ulonglong2 b0 = *(const ulonglong2*)bp;
        ulonglong2 b1 = *(const ulonglong2*)(bp + 4);
        float av[8] = {a0.x, a0.y, a0.z, a0.w, a1.x, a1.y, a1.z, a1.w};
        #pragma unroll
        for (int i = 0; i < 8; i++) {
            u64 ad = pack2(av[i], av[i]);
            acc[i][0] = fma2(ad, b0.x, acc[i][0]);
            acc[i][1] = fma2(ad, b0.y, acc[i][1]);
            acc[i][2] = fma2(ad, b1.x, acc[i][2]);
            acc[i][3] = fma2(ad, b1.y, acc[i][3]);
        }
    }
}

// ---------------- split-K SYRK: 128x128 tiles, coalesced loads -----------------
// grid (2, 2, Bz*KSsplit); atomic reduce into g_R; row sums fused (by==0).
__global__ __launch_bounds__(256, 2) void k_syrk(const float* __restrict__ bimg) {
    extern __shared__ __align__(16) float sm[];
    float* Asm = sm;                // 2 * TBUF
    float* Bsm = sm + 2 * TBUF;     // 2 * TBUF
    int ti = blockIdx.x * 128;
    int tj = blockIdx.y * 128;
    int bz = blockIdx.z >> 4;
    int ks = blockIdx.z & (KSsplit - 1);
    const float* Bb = bimg + (size_t)bz * Cc * Nn;
    int tid = threadIdx.x;
    int lane = tid & 31, warp = tid >> 5;
    int rbase = warp * 16 + (lane >> 4) * 8;
    int cbase = (lane & 15) * 8;
    int k0 = ks * KPB;

    // coalesced load map (R4-proven): e = tid + l*256 -> row e>>3, k (e&7)*4
    int er[4], ek[4];
    #pragma unroll
    for (int l = 0; l < 4; l++) { int e = tid + l * 256; er[l] = e >> 3; ek[l] = (e & 7) * 4; }

    float4 va[4], vb[4];
    u64 acc[8][4] = {};
    float rs[4] = {0.f, 0.f, 0.f, 0.f};

    #define SY_LOAD(t) do { \
        int kb = k0 + (t) * 32; \
        _Pragma("unroll") for (int l = 0; l < 4; l++) { \
            va[l] = *(const float4*)&Bb[(size_t)(ti + er[l]) * Nn + kb + ek[l]]; \
            vb[l] = *(const float4*)&Bb[(size_t)(tj + er[l]) * Nn + kb + ek[l]]; \
        } \
    } while (0)

    #define SY_STORE(buf) do { \
        _Pragma("unroll") for (int l = 0; l < 4; l++) { \
            float ta[4]; *(float4*)ta = va[l]; \
            float tb[4]; *(float4*)tb = vb[l]; \
            rs[l] += ta[0] + ta[1] + ta[2] + ta[3]; \
            _Pragma("unroll") for (int q = 0; q < 4; q++) { \
                Asm[(buf) * TBUF + (ek[l] + q) * PAD + er[l]] = ta[q]; \
                Bsm[(buf) * TBUF + (ek[l] + q) * PAD + er[l]] = tb[q]; \
            } \
        } \
    } while (0)

    const int T = KPB / 32;   // 8
    SY_LOAD(0);
    SY_STORE(0);
    SY_LOAD(1);
    __syncthreads();
    #pragma unroll 1
    for (int t = 0; t < T; t++) {
        mm128(&Asm[(t & 1) * TBUF], &Bsm[(t & 1) * TBUF], rbase, cbase, acc);
        if (t + 1 < T) SY_STORE((t + 1) & 1);
        __syncthreads();
        if (t + 2 < T) SY_LOAD(t + 2);
    }
    #undef SY_LOAD
    #undef SY_STORE

    if (blockIdx.y == 0) {
        #pragma unroll
        for (int l = 0; l < 4; l++)
            atomicAdd(&g_s[bz * Cc + ti + er[l]], rs[l]);
    }

    float* Rb = g_R + (size_t)bz * Cc * Cc;
    #pragma unroll
    for (int i = 0; i < 8; i++) {
        int row = ti + rbase + i;
        float* dst = &Rb[(size_t)row * Cc + tj + cbase];
        #pragma unroll
        for (int j = 0; j < 4; j++) {
            float2 p = unpack2(acc[i][j]);
            atomicAdd(dst + j * 2 + 0, p.x);
            atomicAdd(dst + j * 2 + 1, p.y);
        }
    }
}

// ---------------- generic small batched GEMM (32x32 tiles, R4) -----------------
__global__ __launch_bounds__(256) void k_gemm32(
    const float* __restrict__ A, long long sA,
    const float* __restrict__ B, long long sB,
    float* __restrict__ C, long long sC,
    int M, int N, int K, int BT, float scale,
    const float* __restrict__ r1a, long long s1a,
    const float* __restrict__ r1b, long long s1b,
    const float* __restrict__ r2a, long long s2a,
    const float* __restrict__ r2b, long long s2b)
{
    int m0 = blockIdx.x * 32, n0 = blockIdx.y * 32, bz = blockIdx.z;
    A += (size_t)bz * sA; B += (size_t)bz * sB; C += (size_t)bz * sC;
    __shared__ float As[32][33], Bs[32][33];
    int tid = threadIdx.x, tx = tid & 15, ty = tid >> 4;
    float acc00 = 0.f, acc01 = 0.f, acc10 = 0.f, acc11 = 0.f;
    for (int k0 = 0; k0 < K; k0 += 32) {
        #pragma unroll
        for (int l = 0; l < 4; l++) {
            int idx = tid + l * 256;
            int r = idx >> 5, k = idx & 31;
            As[k][r] = A[(size_t)(m0 + r) * K + k0 + k];
            if (!BT) Bs[r][k] = B[(size_t)(k0 + r) * N + n0 + k];
            else     Bs[k][r] = B[(size_t)(n0 + r) * K + k0 + k];
        }
        __syncthreads();
        #pragma unroll
        for (int k = 0; k < 32; k++) {
            float a0 = As[k][ty * 2], a1 = As[k][ty * 2 + 1];
            float b0 = Bs[k][tx * 2], b1 = Bs[k][tx * 2 + 1];
            acc00 += a0 * b0; acc01 += a0 * b1;
            acc10 += a1 * b0; acc11 += a1 * b1;
        }
        __syncthreads();
    }
    float e[2][2] = {{acc00, acc01}, {acc10, acc11}};
    #pragma unroll
    for (int ii = 0; ii < 2; ii++)
        #pragma unroll
        for (int jj = 0; jj < 2; jj++) {
            int m = m0 + ty * 2 + ii, n = n0 + tx * 2 + jj;
            float v = e[ii][jj] * scale;
            if (r1a)
                v += r1a[(size_t)bz * s1a + m] * r1b[(size_t)bz * s1b + n]
                   + r2a[(size_t)bz * s2a + m] * r2b[(size_t)bz * s2b + n];
            C[(size_t)m * N + n] = v;
        }
}

// ---------------- 64x64-tile batched GEMM (proven R7/R9) -----------------------
#define CPAD 68
#define CBUF (32 * CPAD)
__global__ __launch_bounds__(256) void k_mm64(
    const float* __restrict__ A, long long sA, int lda,
    const float* __restrict__ B, long long sB, int ldb,
    float* __restrict__ C, long long sC, int N, int K, float scale)
{
    __shared__ __align__(16) float As[2 * CBUF], Bs[2 * CBUF];
    int m0 = blockIdx.x * 64, n0 = blockIdx.y * 64, bz = blockIdx.z;
    A += (size_t)bz * sA; B += (size_t)bz * sB; C += (size_t)bz * sC;
    int tid = threadIdx.x;
    int lane = tid & 31, warp = tid >> 5;
    int rbase = warp * 8 + (lane >> 4) * 4;
    int cbase = (lane & 15) * 4;
    int ar = tid & 63, akg = tid >> 6;
    u64 acc[4][2] = {};
    float4 va[2], vb[2];

    #define CM_LOAD(t) do { \
        int kb = (t) * 32; \
        _Pragma("unroll") for (int l = 0; l < 2; l++) \
            va[l] = *(const float4*)&A[(size_t)(m0 + ar) * lda + kb + akg * 4 + l * 16]; \
        _Pragma("unroll") for (int l = 0; l < 2; l++) { \
            int e = tid + l * 256; \
            vb[l] = *(const float4*)&B[(size_t)(kb + (e >> 4)) * ldb + n0 + (e & 15) * 4]; \
        } \
    } while (0)

    #define CM_STORE(buf) do { \
        _Pragma("unroll") for (int l = 0; l < 2; l++) { \
            float tv[4]; *(float4*)tv = va[l]; \
            _Pragma("unroll") for (int q = 0; q < 4; q++) \
                As[(buf) * CBUF + (akg * 4 + l * 16 + q) * CPAD + ar] = tv[q]; \
        } \
        _Pragma("unroll") for (int l = 0; l < 2; l++) { \
            int e = tid + l * 256; \
            *(float4*)&Bs[(buf) * CBUF + (e >> 4) * CPAD + (e & 15) * 4] = vb[l]; \
        } \
    } while (0)

    const int T = K / 32;
    CM_LOAD(0);
    CM_STORE(0);
    if (T > 1) CM_LOAD(1);
    __syncthreads();
    #pragma unroll 1
    for (int t = 0; t < T; t++) {
        const float* Ab = &As[(t & 1) * CBUF];
        const float* Bb2 = &Bs[(t & 1) * CBUF];
        #pragma unroll 8
        for (int k = 0; k < 32; k++) {
            float4 a = *(const float4*)&Ab[k * CPAD + rbase];
            ulonglong2 bv = *(const ulonglong2*)&Bb2[k * CPAD + cbase];
            float av[4] = {a.x, a.y, a.z, a.w};
            #pragma unroll
            for (int i = 0; i < 4; i++) {
                u64 ad = pack2(av[i], av[i]);
                acc[i][0] = fma2(ad, bv.x, acc[i][0]);
                acc[i][1] = fma2(ad, bv.y, acc[i][1]);
            }
        }
        if (t + 1 < T) CM_STORE((t + 1) & 1);
        __syncthreads();
        if (t + 2 < T) CM_LOAD(t + 2);
    }
    #undef CM_LOAD
    #undef CM_STORE

    #pragma unroll
    for (int i = 0; i < 4; i++) {
        int m = m0 + rbase + i;
        float2 p0 = unpack2(acc[i][0]), p1 = unpack2(acc[i][1]);
        float4 v = make_float4(p0.x * scale, p0.y * scale, p1.x * scale, p1.y * scale);
        *(float4*)&C[(size_t)m * N + n0 + cbase] = v;
    }
}

// ---------------- fold theta_b + BN into per-(b,c) bias & alpha ----------------
__global__ __launch_bounds__(256) void k_dvec(
    const float* __restrict__ theta_b, const float* __restrict__ gamma,
    const float* __restrict__ beta, const float* __restrict__ mean,
    const float* __restrict__ var)
{
    int b = blockIdx.x, c = threadIdx.x;
    const float* Trow = g_T + ((size_t)b * Cc + c) * Cii;
    float d = 0.f;
    for (int i = 0; i < Cii; i++) d += Trow[i] * theta_b[i];
    float al = gamma[c] * rsqrtf(var[c] + 1e-5f);
    g_dp[b * Cc + c] = al * (d - mean[c]) + beta[c];
    if (b == 0) g_alpha[c] = al;
}

// ---------------- final: out[b] = alpha .* (Q[b] @ A[b]) + dp ------------------
// grid (2, 32, Bz); 128(c) x 128(n) tiles; Q coalesced+transposed, A natural.
__global__ __launch_bounds__(256, 2) void k_out(const float* __restrict__ aimg,
                                                float* __restrict__ out)
{
    extern __shared__ __align__(16) float sm[];
    float* Qs  = sm;                // 2 * TBUF
    float* Asn = sm + 2 * TBUF;     // 2 * TBUF
    int tc = blockIdx.x * 128;
    int tn = blockIdx.y * 128;
    int bz = blockIdx.z;
    const float* Ab = aimg + (size_t)bz * Cc * Nn;
    const float* Qb = g_Q + (size_t)bz * Cc * Cc;
    int tid = threadIdx.x;
    int lane = tid & 31, warp = tid >> 5;
    int rbase = warp * 16 + (lane >> 4) * 8;
    int cbase = (lane & 15) * 8;

    int er[4], ek[4], akr[4], anq[4];
    #pragma unroll
    for (int l = 0; l < 4; l++) {
        int e = tid + l * 256;
        er[l] = e >> 3; ek[l] = (e & 7) * 4;      // Q tile map
        akr[l] = e >> 5; anq[l] = (e & 31) * 4;   // A tile map
    }

    float4 vq[4], va[4];
    u64 acc[8][4] = {};

    #define FO_LOAD(t) do { \
        int kb = (t) * 32; \
        _Pragma("unroll") for (int l = 0; l < 4; l++) { \
            vq[l] = *(const float4*)&Qb[(size_t)(tc + er[l]) * Cc + kb + ek[l]]; \
            va[l] = *(const float4*)&Ab[(size_t)(kb + akr[l]) * Nn + tn + anq[l]]; \
        } \
    } while (0)

    #define FO_STORE(buf) do { \
        _Pragma("unroll") for (int l = 0; l < 4; l++) { \
            float tv[4]; *(float4*)tv = vq[l]; \
            _Pragma("unroll") for (int q = 0; q < 4; q++) \
                Qs[(buf) * TBUF + (ek[l] + q) * PAD + er[l]] = tv[q]; \
            *(float4*)&Asn[(buf) * TBUF + akr[l] * PAD + anq[l]] = va[l]; \
        } \
    } while (0)

    const int T = Cc / 32;   // 8
    FO_LOAD(0);
    FO_STORE(0);
    FO_LOAD(1);
    __syncthreads();
    #pragma unroll 1
    for (int t = 0; t < T; t++) {
        mm128(&Qs[(t & 1) * TBUF], &Asn[(t & 1) * TBUF], rbase, cbase, acc);
        if (t + 1 < T) FO_STORE((t + 1) & 1);
        __syncthreads();
        if (t + 2 < T) FO_LOAD(t + 2);
    }
    #undef FO_LOAD
    #undef FO_STORE

    float* outb = out + (size_t)bz * Cc * Nn;
    #pragma unroll
    for (int i = 0; i < 8; i++) {
        int c = tc + rbase + i;
        float al = g_alpha[c];
        float dpv = g_dp[bz * Cc + c];
        float2 p0 = unpack2(acc[i][0]), p1 = unpack2(acc[i][1]);
        float2 p2 = unpack2(acc[i][2]), p3 = unpack2(acc[i][3]);
        float* dst = &outb[(size_t)c * Nn + tn + cbase];
        *(float4*)dst = make_float4(al * p0.x + dpv, al * p0.y + dpv,
                                    al * p1.x + dpv, al * p1.y + dpv);
        *(float4*)(dst + 4) = make_float4(al * p2.x + dpv, al * p2.y + dpv,
                                          al * p3.x + dpv, al * p3.y + dpv);
    }
}

// -----------------------------------------------------------------------------
extern "C" void kernel_launch(void* const* d_in, const int* in_sizes, int n_in,
                              void* d_out, int out_size) {
    (void)in_sizes; (void)n_in; (void)out_size;
    const float* a       = (const float*)d_in[0];
    const float* bimg    = (const float*)d_in[1];
    const float* theta_w = (const float*)d_in[2];
    const float* theta_b = (const float*)d_in[3];
    const float* phi_w   = (const float*)d_in[4];
    const float* phi_b   = (const float*)d_in[5];
    const float* g_wp    = (const float*)d_in[6];
    const float* g_bp    = (const float*)d_in[7];
    const float* W_wp    = (const float*)d_in[8];
    const float* gamma   = (const float*)d_in[9];
    const float* beta    = (const float*)d_in[10];
    const float* mean    = (const float*)d_in[11];
    const float* var     = (const float*)d_in[12];

    static int attr_done = 0;
    if (!attr_done) {
        cudaFuncSetAttribute(k_syrk, cudaFuncAttributeMaxDynamicSharedMemorySize, SMEM_BIG);
        cudaFuncSetAttribute(k_out,  cudaFuncAttributeMaxDynamicSharedMemorySize, SMEM_BIG);
        attr_done = 1;
    }

    float *pR, *pU, *pS, *pT, *pQ, *pGs, *pPs2;
    cudaGetSymbolAddress((void**)&pR,   g_R);
    cudaGetSymbolAddress((void**)&pU,   g_U);
    cudaGetSymbolAddress((void**)&pS,   g_S);
    cudaGetSymbolAddress((void**)&pT,   g_T);
    cudaGetSymbolAddress((void**)&pQ,   g_Q);
    cudaGetSymbolAddress((void**)&pGs,  g_gs);
    cudaGetSymbolAddress((void**)&pPs2, g_ps2);

    k_zero<<<(Bz * Cc * Cc / 4) / 256, 256>>>();
    k_syrk<<<dim3(2, 2, Bz * KSsplit), 256, SMEM_BIG>>>(bimg);
    k_gsps<<<Bz, 256>>>(g_wp, phi_w, phi_b);

    // U[b] = g_w @ R[b]      [128,256], K=256
    k_mm64<<<dim3(Cii / 64, Cc / 64, Bz), 256>>>(
        g_wp, 0, Cc, pR, (long long)Cc * Cc, Cc,
        pU, (long long)Cii * Cc, Cc, Cc, 1.f);
    // S[b] = U[b] @ phi_w^T + gs*phib^T + gb*ps2^T   [128,128], K=256 (needs BT)
    k_gemm32<<<dim3(Cii / 32, Cii / 32, Bz), 256>>>(
        pU, (long long)Cii * Cc, phi_w, 0, pS, (long long)Cii * Cii,
        Cii, Cii, Cc, 1, 1.f,
        pGs, Cii, phi_b, 0, g_bp, 0, pPs2, Cii);
    // T[b] = W_w @ S[b] / N   [256,128], K=128
    k_mm64<<<dim3(Cc / 64, Cii / 64, Bz), 256>>>(
        W_wp, 0, Cii, pS, (long long)Cii * Cii, Cii,
        pT, (long long)Cc * Cii, Cii, Cii, 1.f / (float)Nn);
    // Q[b] = T[b] @ theta_w   [256,256], K=128
    k_mm64<<<dim3(Cc / 64, Cc / 64, Bz), 256>>>(
        pT, (long long)Cc * Cii, Cii, theta_w, 0, Cc,
        pQ, (long long)Cc * Cc, Cc, Cii, 1.f);

    k_dvec<<<Bz, 256>>>(theta_b, gamma, beta, mean, var);
    k_out<<<dim3(2, 32, Bz), 256, SMEM_BIG>>>(a, (float*)d_out);
}

// round 16
// speedup vs baseline: 1.5951x; 1.5951x over previous
#include <cuda_runtime.h>

#define Bz 4
#define Cc 256
#define Cii 128
#define Nn 4096
#define KSsplit 16
#define KPB (Nn / KSsplit)   // 256 K per split block

typedef unsigned long long u64;

__device__ __forceinline__ u64 pack2(float lo, float hi) {
    u64 r; asm("mov.b64 %0, {%1,%2};" : "=l"(r) : "f"(lo), "f"(hi)); return r;
}
__device__ __forceinline__ float2 unpack2(u64 v) {
    float2 f; asm("mov.b64 {%0,%1}, %2;" : "=f"(f.x), "=f"(f.y) : "l"(v)); return f;
}
__device__ __forceinline__ u64 fma2(u64 a, u64 b, u64 c) {
    u64 d; asm("fma.rn.f32x2 %0, %1, %2, %3;" : "=l"(d) : "l"(a), "l"(b), "l"(c)); return d;
}

// ---------------- scratch (static device globals; no allocation) -------------
__device__ float g_R[Bz * Cc * Cc];                 // R = B B^T (atomics)
__device__ float g_s[Bz * Cc];                      // row sums of b image (atomics)
__device__ float g_gs[Bz * Cii];                    // g_w @ s
__device__ float g_ps2[Bz * Cii];                   // phi_w @ s + N*phi_b
__device__ float g_U[Bz * Cii * Cc];                // g_w @ R
__device__ float g_S[Bz * Cii * Cii];               // U @ phi_w^T + rank1
__device__ float g_T[Bz * Cc * Cii];                // W_w @ S / N
__device__ float g_Q[Bz * Cc * Cc];                 // T @ theta_w
__device__ float g_dp[Bz * Cc];                     // folded bias (BN included)
__device__ float g_alpha[Cc];                       // BN scale

// ---------------- 128x128 tile geometry ---------------------------------------
#define PAD 132
#define TBUF (32 * PAD)
#define SMEM_BIG (4 * TBUF * 4)   // two tiles, double buffered: 67584 B

// ---------------- zero the atomic-reduce targets ------------------------------
__global__ __launch_bounds__(256) void k_zero() {
    int i = blockIdx.x * 256 + threadIdx.x;
    ((float4*)g_R)[i] = make_float4(0.f, 0.f, 0.f, 0.f);
    if (i < (Bz * Cc) / 4) ((float4*)g_s)[i] = make_float4(0.f, 0.f, 0.f, 0.f);
}

// ---------------- gs = g_w @ s ; ps2 = phi_w @ s + N*phi_b -------------------
__global__ __launch_bounds__(256) void k_gsps(const float* __restrict__ gw,
                                              const float* __restrict__ phiw,
                                              const float* __restrict__ phib) {
    int b = blockIdx.x;
    int tid = threadIdx.x;
    __shared__ float ssh[Cc];
    ssh[tid] = g_s[b * Cc + tid];
    __syncthreads();
    if (tid < Cii) {
        float acc = 0.f;
        for (int c = 0; c < Cc; c++) acc += gw[tid * Cc + c] * ssh[c];
        g_gs[b * Cii + tid] = acc;
    } else {
        int i = tid - Cii;
        float acc = 0.f;
        for (int c = 0; c < Cc; c++) acc += phiw[i * Cc + c] * ssh[c];
        g_ps2[b * Cii + i] = acc + (float)Nn * phib[i];
    }
}

// ---------------- 128x128 micro kernel (verified in R7) ------------------------
__device__ __forceinline__ void mm128(const float* __restrict__ As,
                                      const float* __restrict__ Bs,
                                      int rbase, int cbase, u64 acc[8][4]) {
    #pragma unroll 8
    for (int k = 0; k < 32; k++) {
        const float* ap = &As[k * PAD + rbase];
        const float* bp = &Bs[k * PAD + cbase];
        float4 a0 = *(const float4*)ap;
        float4 a1 = *(const float4*)(ap + 4);
        ulonglong2 b0 = *(const ulonglong2*)bp;
        ulonglong2 b1 = *(const ulonglong2*)(bp + 4);
        float av[8] = {a0.x, a0.y, a0.z, a0.w, a1.x, a1.y, a1.z, a1.w};
        #pragma unroll
        for (int i = 0; i < 8; i++) {
            u64 ad = pack2(av[i], av[i]);
            acc[i][0] = fma2(ad, b0.x, acc[i][0]);
            acc[i][1] = fma2(ad, b0.y, acc[i][1]);
            acc[i][2] = fma2(ad, b1.x, acc[i][2]);
            acc[i][3] = fma2(ad, b1.y, acc[i][3]);
        }
    }
}

// ---------------- split-K SYRK: 128x128 tiles, coalesced loads -----------------
// grid (2, 2, Bz*KSsplit); atomic reduce into g_R; row sums fused (by==0).
__global__ __launch_bounds__(256, 2) void k_syrk(const float* __restrict__ bimg) {
    extern __shared__ __align__(16) float sm[];
    float* Asm = sm;                // 2 * TBUF
    float* Bsm = sm + 2 * TBUF;     // 2 * TBUF
    int ti = blockIdx.x * 128;
    int tj = blockIdx.y * 128;
    int bz = blockIdx.z >> 4;
    int ks = blockIdx.z & (KSsplit - 1);
    const float* Bb = bimg + (size_t)bz * Cc * Nn;
    int tid = threadIdx.x;
    int lane = tid & 31, warp = tid >> 5;
    int rbase = warp * 16 + (lane >> 4) * 8;
    int cbase = (lane & 15) * 8;
    int k0 = ks * KPB;

    // coalesced load map (R4-proven): e = tid + l*256 -> row e>>3, k (e&7)*4
    int er[4], ek[4];
    #pragma unroll
    for (int l = 0; l < 4; l++) { int e = tid + l * 256; er[l] = e >> 3; ek[l] = (e & 7) * 4; }

    float4 va[4], vb[4];
    u64 acc[8][4] = {};
    float rs[4] = {0.f, 0.f, 0.f, 0.f};

    #define SY_LOAD(t) do { \
        int kb = k0 + (t) * 32; \
        _Pragma("unroll") for (int l = 0; l < 4; l++) { \
            va[l] = *(const float4*)&Bb[(size_t)(ti + er[l]) * Nn + kb + ek[l]]; \
            vb[l] = *(const float4*)&Bb[(size_t)(tj + er[l]) * Nn + kb + ek[l]]; \
        } \
    } while (0)

    #define SY_STORE(buf) do { \
        _Pragma("unroll") for (int l = 0; l < 4; l++) { \
            float ta[4]; *(float4*)ta = va[l]; \
            float tb[4]; *(float4*)tb = vb[l]; \
            rs[l] += ta[0] + ta[1] + ta[2] + ta[3]; \
            _Pragma("unroll") for (int q = 0; q < 4; q++) { \
                Asm[(buf) * TBUF + (ek[l] + q) * PAD + er[l]] = ta[q]; \
                Bsm[(buf) * TBUF + (ek[l] + q) * PAD + er[l]] = tb[q]; \
            } \
        } \
    } while (0)

    const int T = KPB / 32;   // 8
    SY_LOAD(0);
    SY_STORE(0);
    SY_LOAD(1);
    __syncthreads();
    #pragma unroll 1
    for (int t = 0; t < T; t++) {
        mm128(&Asm[(t & 1) * TBUF], &Bsm[(t & 1) * TBUF], rbase, cbase, acc);
        if (t + 1 < T) SY_STORE((t + 1) & 1);
        __syncthreads();
        if (t + 2 < T) SY_LOAD(t + 2);
    }
    #undef SY_LOAD
    #undef SY_STORE

    if (blockIdx.y == 0) {
        #pragma unroll
        for (int l = 0; l < 4; l++)
            atomicAdd(&g_s[bz * Cc + ti + er[l]], rs[l]);
    }

    float* Rb = g_R + (size_t)bz * Cc * Cc;
    #pragma unroll
    for (int i = 0; i < 8; i++) {
        int row = ti + rbase + i;
        float* dst = &Rb[(size_t)row * Cc + tj + cbase];
        #pragma unroll
        for (int j = 0; j < 4; j++) {
            float2 p = unpack2(acc[i][j]);
            atomicAdd(dst + j * 2 + 0, p.x);
            atomicAdd(dst + j * 2 + 1, p.y);
        }
    }
}

// ---------------- generic small batched GEMM (32x32 tiles, R4) -----------------
__global__ __launch_bounds__(256) void k_gemm32(
    const float* __restrict__ A, long long sA,
    const float* __restrict__ B, long long sB,
    float* __restrict__ C, long long sC,
    int M, int N, int K, int BT, float scale,
    const float* __restrict__ r1a, long long s1a,
    const float* __restrict__ r1b, long long s1b,
    const float* __restrict__ r2a, long long s2a,
    const float* __restrict__ r2b, long long s2b)
{
    int m0 = blockIdx.x * 32, n0 = blockIdx.y * 32, bz = blockIdx.z;
    A += (size_t)bz * sA; B += (size_t)bz * sB; C += (size_t)bz * sC;
    __shared__ float As[32][33], Bs[32][33];
    int tid = threadIdx.x, tx = tid & 15, ty = tid >> 4;
    float acc00 = 0.f, acc01 = 0.f, acc10 = 0.f, acc11 = 0.f;
    for (int k0 = 0; k0 < K; k0 += 32) {
        #pragma unroll
        for (int l = 0; l < 4; l++) {
            int idx = tid + l * 256;
            int r = idx >> 5, k = idx & 31;
            As[k][r] = A[(size_t)(m0 + r) * K + k0 + k];
            if (!BT) Bs[r][k] = B[(size_t)(k0 + r) * N + n0 + k];
            else     Bs[k][r] = B[(size_t)(n0 + r) * K + k0 + k];
        }
        __syncthreads();
        #pragma unroll
        for (int k = 0; k < 32; k++) {
            float a0 = As[k][ty * 2], a1 = As[k][ty * 2 + 1];
            float b0 = Bs[k][tx * 2], b1 = Bs[k][tx * 2 + 1];
            acc00 += a0 * b0; acc01 += a0 * b1;
            acc10 += a1 * b0; acc11 += a1 * b1;
        }
        __syncthreads();
    }
    float e[2][2] = {{acc00, acc01}, {acc10, acc11}};
    #pragma unroll
    for (int ii = 0; ii < 2; ii++)
        #pragma unroll
        for (int jj = 0; jj < 2; jj++) {
            int m = m0 + ty * 2 + ii, n = n0 + tx * 2 + jj;
            float v = e[ii][jj] * scale;
            if (r1a)
                v += r1a[(size_t)bz * s1a + m] * r1b[(size_t)bz * s1b + n]
                   + r2a[(size_t)bz * s2a + m] * r2b[(size_t)bz * s2b + n];
            C[(size_t)m * N + n] = v;
        }
}

// ---------------- 64x64-tile batched GEMM (proven R7/R9) -----------------------
#define CPAD 68
#define CBUF (32 * CPAD)
__global__ __launch_bounds__(256) void k_mm64(
    const float* __restrict__ A, long long sA, int lda,
    const float* __restrict__ B, long long sB, int ldb,
    float* __restrict__ C, long long sC, int N, int K, float scale)
{
    __shared__ __align__(16) float As[2 * CBUF], Bs[2 * CBUF];
    int m0 = blockIdx.x * 64, n0 = blockIdx.y * 64, bz = blockIdx.z;
    A += (size_t)bz * sA; B += (size_t)bz * sB; C += (size_t)bz * sC;
    int tid = threadIdx.x;
    int lane = tid & 31, warp = tid >> 5;
    int rbase = warp * 8 + (lane >> 4) * 4;
    int cbase = (lane & 15) * 4;
    int ar = tid & 63, akg = tid >> 6;
    u64 acc[4][2] = {};
    float4 va[2], vb[2];

    #define CM_LOAD(t) do { \
        int kb = (t) * 32; \
        _Pragma("unroll") for (int l = 0; l < 2; l++) \
            va[l] = *(const float4*)&A[(size_t)(m0 + ar) * lda + kb + akg * 4 + l * 16]; \
        _Pragma("unroll") for (int l = 0; l < 2; l++) { \
            int e = tid + l * 256; \
            vb[l] = *(const float4*)&B[(size_t)(kb + (e >> 4)) * ldb + n0 + (e & 15) * 4]; \
        } \
    } while (0)

    #define CM_STORE(buf) do { \
        _Pragma("unroll") for (int l = 0; l < 2; l++) { \
            float tv[4]; *(float4*)tv = va[l]; \
            _Pragma("unroll") for (int q = 0; q < 4; q++) \
                As[(buf) * CBUF + (akg * 4 + l * 16 + q) * CPAD + ar] = tv[q]; \
        } \
        _Pragma("unroll") for (int l = 0; l < 2; l++) { \
            int e = tid + l * 256; \
            *(float4*)&Bs[(buf) * CBUF + (e >> 4) * CPAD + (e & 15) * 4] = vb[l]; \
        } \
    } while (0)

    const int T = K / 32;
    CM_LOAD(0);
    CM_STORE(0);
    if (T > 1) CM_LOAD(1);
    __syncthreads();
    #pragma unroll 1
    for (int t = 0; t < T; t++) {
        const float* Ab = &As[(t & 1) * CBUF];
        const float* Bb2 = &Bs[(t & 1) * CBUF];
        #pragma unroll 8
        for (int k = 0; k < 32; k++) {
            float4 a = *(const float4*)&Ab[k * CPAD + rbase];
            ulonglong2 bv = *(const ulonglong2*)&Bb2[k * CPAD + cbase];
            float av[4] = {a.x, a.y, a.z, a.w};
            #pragma unroll
            for (int i = 0; i < 4; i++) {
                u64 ad = pack2(av[i], av[i]);
                acc[i][0] = fma2(ad, bv.x, acc[i][0]);
                acc[i][1] = fma2(ad, bv.y, acc[i][1]);
            }
        }
        if (t + 1 < T) CM_STORE((t + 1) & 1);
        __syncthreads();
        if (t + 2 < T) CM_LOAD(t + 2);
    }
    #undef CM_LOAD
    #undef CM_STORE

    #pragma unroll
    for (int i = 0; i < 4; i++) {
        int m = m0 + rbase + i;
        float2 p0 = unpack2(acc[i][0]), p1 = unpack2(acc[i][1]);
        float4 v = make_float4(p0.x * scale, p0.y * scale, p1.x * scale, p1.y * scale);
        *(float4*)&C[(size_t)m * N + n0 + cbase] = v;
    }
}

// ---------------- fold theta_b + BN into per-(b,c) bias & alpha ----------------
__global__ __launch_bounds__(256) void k_dvec(
    const float* __restrict__ theta_b, const float* __restrict__ gamma,
    const float* __restrict__ beta, const float* __restrict__ mean,
    const float* __restrict__ var)
{
    int b = blockIdx.x, c = threadIdx.x;
    const float* Trow = g_T + ((size_t)b * Cc + c) * Cii;
    float d = 0.f;
    for (int i = 0; i < Cii; i++) d += Trow[i] * theta_b[i];
    float al = gamma[c] * rsqrtf(var[c] + 1e-5f);
    g_dp[b * Cc + c] = al * (d - mean[c]) + beta[c];
    if (b == 0) g_alpha[c] = al;
}

// ---------------- final: out[b] = alpha .* (Q[b] @ A[b]) + dp ------------------
// grid (2, 32, Bz); 128(c) x 128(n) tiles; Q coalesced+transposed, A natural.
__global__ __launch_bounds__(256, 2) void k_out(const float* __restrict__ aimg,
                                                float* __restrict__ out)
{
    extern __shared__ __align__(16) float sm[];
    float* Qs  = sm;                // 2 * TBUF
    float* Asn = sm + 2 * TBUF;     // 2 * TBUF
    int tc = blockIdx.x * 128;
    int tn = blockIdx.y * 128;
    int bz = blockIdx.z;
    const float* Ab = aimg + (size_t)bz * Cc * Nn;
    const float* Qb = g_Q + (size_t)bz * Cc * Cc;
    int tid = threadIdx.x;
    int lane = tid & 31, warp = tid >> 5;
    int rbase = warp * 16 + (lane >> 4) * 8;
    int cbase = (lane & 15) * 8;

    int er[4], ek[4], akr[4], anq[4];
    #pragma unroll
    for (int l = 0; l < 4; l++) {
        int e = tid + l * 256;
        er[l] = e >> 3; ek[l] = (e & 7) * 4;      // Q tile map
        akr[l] = e >> 5; anq[l] = (e & 31) * 4;   // A tile map
    }

    float4 vq[4], va[4];
    u64 acc[8][4] = {};

    #define FO_LOAD(t) do { \
        int kb = (t) * 32; \
        _Pragma("unroll") for (int l = 0; l < 4; l++) { \
            vq[l] = *(const float4*)&Qb[(size_t)(tc + er[l]) * Cc + kb + ek[l]]; \
            va[l] = *(const float4*)&Ab[(size_t)(kb + akr[l]) * Nn + tn + anq[l]]; \
        } \
    } while (0)

    #define FO_STORE(buf) do { \
        _Pragma("unroll") for (int l = 0; l < 4; l++) { \
            float tv[4]; *(float4*)tv = vq[l]; \
            _Pragma("unroll") for (int q = 0; q < 4; q++) \
                Qs[(buf) * TBUF + (ek[l] + q) * PAD + er[l]] = tv[q]; \
            *(float4*)&Asn[(buf) * TBUF + akr[l] * PAD + anq[l]] = va[l]; \
        } \
    } while (0)

    const int T = Cc / 32;   // 8
    FO_LOAD(0);
    FO_STORE(0);
    FO_LOAD(1);
    __syncthreads();
    #pragma unroll 1
    for (int t = 0; t < T; t++) {
        mm128(&Qs[(t & 1) * TBUF], &Asn[(t & 1) * TBUF], rbase, cbase, acc);
        if (t + 1 < T) FO_STORE((t + 1) & 1);
        __syncthreads();
        if (t + 2 < T) FO_LOAD(t + 2);
    }
    #undef FO_LOAD
    #undef FO_STORE

    float* outb = out + (size_t)bz * Cc * Nn;
    #pragma unroll
    for (int i = 0; i < 8; i++) {
        int c = tc + rbase + i;
        float al = g_alpha[c];
        float dpv = g_dp[bz * Cc + c];
        float2 p0 = unpack2(acc[i][0]), p1 = unpack2(acc[i][1]);
        float2 p2 = unpack2(acc[i][2]), p3 = unpack2(acc[i][3]);
        float* dst = &outb[(size_t)c * Nn + tn + cbase];
        *(float4*)dst = make_float4(al * p0.x + dpv, al * p0.y + dpv,
                                    al * p1.x + dpv, al * p1.y + dpv);
        *(float4*)(dst + 4) = make_float4(al * p2.x + dpv, al * p2.y + dpv,
                                          al * p3.x + dpv, al * p3.y + dpv);
    }
}

// -----------------------------------------------------------------------------
extern "C" void kernel_launch(void* const* d_in, const int* in_sizes, int n_in,
                              void* d_out, int out_size) {
    (void)in_sizes; (void)n_in; (void)out_size;
    const float* a       = (const float*)d_in[0];
    const float* bimg    = (const float*)d_in[1];
    const float* theta_w = (const float*)d_in[2];
    const float* theta_b = (const float*)d_in[3];
    const float* phi_w   = (const float*)d_in[4];
    const float* phi_b   = (const float*)d_in[5];
    const float* g_wp    = (const float*)d_in[6];
    const float* g_bp    = (const float*)d_in[7];
    const float* W_wp    = (const float*)d_in[8];
    const float* gamma   = (const float*)d_in[9];
    const float* beta    = (const float*)d_in[10];
    const float* mean    = (const float*)d_in[11];
    const float* var     = (const float*)d_in[12];

    static int attr_done = 0;
    if (!attr_done) {
        cudaFuncSetAttribute(k_syrk, cudaFuncAttributeMaxDynamicSharedMemorySize, SMEM_BIG);
        cudaFuncSetAttribute(k_out,  cudaFuncAttributeMaxDynamicSharedMemorySize, SMEM_BIG);
        attr_done = 1;
    }

    float *pR, *pU, *pS, *pT, *pQ, *pGs, *pPs2;
    cudaGetSymbolAddress((void**)&pR,   g_R);
    cudaGetSymbolAddress((void**)&pU,   g_U);
    cudaGetSymbolAddress((void**)&pS,   g_S);
    cudaGetSymbolAddress((void**)&pT,   g_T);
    cudaGetSymbolAddress((void**)&pQ,   g_Q);
    cudaGetSymbolAddress((void**)&pGs,  g_gs);
    cudaGetSymbolAddress((void**)&pPs2, g_ps2);

    k_zero<<<(Bz * Cc * Cc / 4) / 256, 256>>>();
    k_syrk<<<dim3(2, 2, Bz * KSsplit), 256, SMEM_BIG>>>(bimg);
    k_gsps<<<Bz, 256>>>(g_wp, phi_w, phi_b);

    // U[b] = g_w @ R[b]      [128,256], K=256
    k_mm64<<<dim3(Cii / 64, Cc / 64, Bz), 256>>>(
        g_wp, 0, Cc, pR, (long long)Cc * Cc, Cc,
        pU, (long long)Cii * Cc, Cc, Cc, 1.f);
    // S[b] = U[b] @ phi_w^T + gs*phib^T + gb*ps2^T   [128,128], K=256 (needs BT)
    k_gemm32<<<dim3(Cii / 32, Cii / 32, Bz), 256>>>(
        pU, (long long)Cii * Cc, phi_w, 0, pS, (long long)Cii * Cii,
        Cii, Cii, Cc, 1, 1.f,
        pGs, Cii, phi_b, 0, g_bp, 0, pPs2, Cii);
    // T[b] = W_w @ S[b] / N   [256,128], K=128
    k_mm64<<<dim3(Cc / 64, Cii / 64, Bz), 256>>>(
        W_wp, 0, Cii, pS, (long long)Cii * Cii, Cii,
        pT, (long long)Cc * Cii, Cii, Cii, 1.f / (float)Nn);
    // Q[b] = T[b] @ theta_w   [256,256], K=128
    k_mm64<<<dim3(Cc / 64, Cc / 64, Bz), 256>>>(
        pT, (long long)Cc * Cii, Cii, theta_w, 0, Cc,
        pQ, (long long)Cc * Cc, Cc, Cii, 1.f);

    k_dvec<<<Bz, 256>>>(theta_b, gamma, beta, mean, var);
    k_out<<<dim3(2, 32, Bz), 256, SMEM_BIG>>>(a, (float*)d_out);
}

// round 17
// speedup vs baseline: 1.5990x; 1.0025x over previous
#include <cuda_runtime.h>

#define Bz 4
#define Cc 256
#define Cii 128
#define Nn 4096
#define KSsplit 16
#define KPB (Nn / KSsplit)   // 256 K per split block

typedef unsigned long long u64;

__device__ __forceinline__ u64 pack2(float lo, float hi) {
    u64 r; asm("mov.b64 %0, {%1,%2};" : "=l"(r) : "f"(lo), "f"(hi)); return r;
}
__device__ __forceinline__ float2 unpack2(u64 v) {
    float2 f; asm("mov.b64 {%0,%1}, %2;" : "=f"(f.x), "=f"(f.y) : "l"(v)); return f;
}
__device__ __forceinline__ u64 fma2(u64 a, u64 b, u64 c) {
    u64 d; asm("fma.rn.f32x2 %0, %1, %2, %3;" : "=l"(d) : "l"(a), "l"(b), "l"(c)); return d;
}

// ---------------- scratch (static device globals; no allocation) -------------
__device__ float g_R[Bz * Cc * Cc];                 // R = B B^T (atomics)
__device__ float g_s[Bz * Cc];                      // row sums of b image (atomics)
__device__ float g_gs[Bz * Cii];                    // g_w @ s
__device__ float g_ps2[Bz * Cii];                   // phi_w @ s + N*phi_b
__device__ float g_U[Bz * Cii * Cc];                // g_w @ R
__device__ float g_S[Bz * Cii * Cii];               // U @ phi_w^T + rank1
__device__ float g_T[Bz * Cc * Cii];                // W_w @ S / N
__device__ float g_Q[Bz * Cc * Cc];                 // T @ theta_w
__device__ float g_dp[Bz * Cc];                     // folded bias (BN included)
__device__ float g_alpha[Cc];                       // BN scale

// ---------------- 128x128 tile geometry ---------------------------------------
#define PAD 132
#define TBUF (32 * PAD)
#define SMEM_BIG (4 * TBUF * 4)   // two tiles, double buffered: 67584 B

// ---------------- zero the atomic-reduce targets ------------------------------
__global__ __launch_bounds__(256) void k_zero() {
    int i = blockIdx.x * 256 + threadIdx.x;
    ((float4*)g_R)[i] = make_float4(0.f, 0.f, 0.f, 0.f);
    if (i < (Bz * Cc) / 4) ((float4*)g_s)[i] = make_float4(0.f, 0.f, 0.f, 0.f);
}

// ---------------- gs = g_w @ s ; ps2 = phi_w @ s + N*phi_b -------------------
__global__ __launch_bounds__(256) void k_gsps(const float* __restrict__ gw,
                                              const float* __restrict__ phiw,
                                              const float* __restrict__ phib) {
    int b = blockIdx.x;
    int tid = threadIdx.x;
    __shared__ float ssh[Cc];
    ssh[tid] = g_s[b * Cc + tid];
    __syncthreads();
    if (tid < Cii) {
        float acc = 0.f;
        for (int c = 0; c < Cc; c++) acc += gw[tid * Cc + c] * ssh[c];
        g_gs[b * Cii + tid] = acc;
    } else {
        int i = tid - Cii;
        float acc = 0.f;
        for (int c = 0; c < Cc; c++) acc += phiw[i * Cc + c] * ssh[c];
        g_ps2[b * Cii + i] = acc + (float)Nn * phib[i];
    }
}

// ---------------- 128x128 micro kernel (verified in R7) ------------------------
__device__ __forceinline__ void mm128(const float* __restrict__ As,
                                      const float* __restrict__ Bs,
                                      int rbase, int cbase, u64 acc[8][4]) {
    #pragma unroll 8
    for (int k = 0; k < 32; k++) {
        const float* ap = &As[k * PAD + rbase];
        const float* bp = &Bs[k * PAD + cbase];
        float4 a0 = *(const float4*)ap;
        float4 a1 = *(const float4*)(ap + 4);
        ulonglong2 b0 = *(const ulonglong2*)bp;
        ulonglong2 b1 = *(const ulonglong2*)(bp + 4);
        float av[8] = {a0.x, a0.y, a0.z, a0.w, a1.x, a1.y, a1.z, a1.w};
        #pragma unroll
        for (int i = 0; i < 8; i++) {
            u64 ad = pack2(av[i], av[i]);
            acc[i][0] = fma2(ad, b0.x, acc[i][0]);
            acc[i][1] = fma2(ad, b0.y, acc[i][1]);
            acc[i][2] = fma2(ad, b1.x, acc[i][2]);
            acc[i][3] = fma2(ad, b1.y, acc[i][3]);
        }
    }
}

// ---------------- split-K SYRK: 128x128 tiles, coalesced loads -----------------
// grid (2, 2, Bz*KSsplit); atomic reduce into g_R; row sums fused (by==0).
__global__ __launch_bounds__(256, 2) void k_syrk(const float* __restrict__ bimg) {
    extern __shared__ __align__(16) float sm[];
    float* Asm = sm;                // 2 * TBUF
    float* Bsm = sm + 2 * TBUF;     // 2 * TBUF
    int ti = blockIdx.x * 128;
    int tj = blockIdx.y * 128;
    int bz = blockIdx.z >> 4;
    int ks = blockIdx.z & (KSsplit - 1);
    const float* Bb = bimg + (size_t)bz * Cc * Nn;
    int tid = threadIdx.x;
    int lane = tid & 31, warp = tid >> 5;
    int rbase = warp * 16 + (lane >> 4) * 8;
    int cbase = (lane & 15) * 8;
    int k0 = ks * KPB;

    // coalesced load map (R4-proven): e = tid + l*256 -> row e>>3, k (e&7)*4
    int er[4], ek[4];
    #pragma unroll
    for (int l = 0; l < 4; l++) { int e = tid + l * 256; er[l] = e >> 3; ek[l] = (e & 7) * 4; }

    float4 va[4], vb[4];
    u64 acc[8][4] = {};
    float rs[4] = {0.f, 0.f, 0.f, 0.f};

    #define SY_LOAD(t) do { \
        int kb = k0 + (t) * 32; \
        _Pragma("unroll") for (int l = 0; l < 4; l++) { \
            va[l] = *(const float4*)&Bb[(size_t)(ti + er[l]) * Nn + kb + ek[l]]; \
            vb[l] = *(const float4*)&Bb[(size_t)(tj + er[l]) * Nn + kb + ek[l]]; \
        } \
    } while (0)

    #define SY_STORE(buf) do { \
        _Pragma("unroll") for (int l = 0; l < 4; l++) { \
            float ta[4]; *(float4*)ta = va[l]; \
            float tb[4]; *(float4*)tb = vb[l]; \
            rs[l] += ta[0] + ta[1] + ta[2] + ta[3]; \
            _Pragma("unroll") for (int q = 0; q < 4; q++) { \
                Asm[(buf) * TBUF + (ek[l] + q) * PAD + er[l]] = ta[q]; \
                Bsm[(buf) * TBUF + (ek[l] + q) * PAD + er[l]] = tb[q]; \
            } \
        } \
    } while (0)

    const int T = KPB / 32;   // 8
    SY_LOAD(0);
    SY_STORE(0);
    SY_LOAD(1);
    __syncthreads();
    #pragma unroll 1
    for (int t = 0; t < T; t++) {
        mm128(&Asm[(t & 1) * TBUF], &Bsm[(t & 1) * TBUF], rbase, cbase, acc);
        if (t + 1 < T) SY_STORE((t + 1) & 1);
        __syncthreads();
        if (t + 2 < T) SY_LOAD(t + 2);
    }
    #undef SY_LOAD
    #undef SY_STORE

    if (blockIdx.y == 0) {
        #pragma unroll
        for (int l = 0; l < 4; l++)
            atomicAdd(&g_s[bz * Cc + ti + er[l]], rs[l]);
    }

    float* Rb = g_R + (size_t)bz * Cc * Cc;
    #pragma unroll
    for (int i = 0; i < 8; i++) {
        int row = ti + rbase + i;
        float* dst = &Rb[(size_t)row * Cc + tj + cbase];
        #pragma unroll
        for (int j = 0; j < 4; j++) {
            float2 p = unpack2(acc[i][j]);
            atomicAdd(dst + j * 2 + 0, p.x);
            atomicAdd(dst + j * 2 + 1, p.y);
        }
    }
}

// ---------------- generic small batched GEMM (32x32 tiles, R4) -----------------
__global__ __launch_bounds__(256) void k_gemm32(
    const float* __restrict__ A, long long sA,
    const float* __restrict__ B, long long sB,
    float* __restrict__ C, long long sC,
    int M, int N, int K, int BT, float scale,
    const float* __restrict__ r1a, long long s1a,
    const float* __restrict__ r1b, long long s1b,
    const float* __restrict__ r2a, long long s2a,
    const float* __restrict__ r2b, long long s2b)
{
    int m0 = blockIdx.x * 32, n0 = blockIdx.y * 32, bz = blockIdx.z;
    A += (size_t)bz * sA; B += (size_t)bz * sB; C += (size_t)bz * sC;
    __shared__ float As[32][33], Bs[32][33];
    int tid = threadIdx.x, tx = tid & 15, ty = tid >> 4;
    float acc00 = 0.f, acc01 = 0.f, acc10 = 0.f, acc11 = 0.f;
    for (int k0 = 0; k0 < K; k0 += 32) {
        #pragma unroll
        for (int l = 0; l < 4; l++) {
            int idx = tid + l * 256;
            int r = idx >> 5, k = idx & 31;
            As[k][r] = A[(size_t)(m0 + r) * K + k0 + k];
            if (!BT) Bs[r][k] = B[(size_t)(k0 + r) * N + n0 + k];
            else     Bs[k][r] = B[(size_t)(n0 + r) * K + k0 + k];
        }
        __syncthreads();
        #pragma unroll
        for (int k = 0; k < 32; k++) {
            float a0 = As[k][ty * 2], a1 = As[k][ty * 2 + 1];
            float b0 = Bs[k][tx * 2], b1 = Bs[k][tx * 2 + 1];
            acc00 += a0 * b0; acc01 += a0 * b1;
            acc10 += a1 * b0; acc11 += a1 * b1;
        }
        __syncthreads();
    }
    float e[2][2] = {{acc00, acc01}, {acc10, acc11}};
    #pragma unroll
    for (int ii = 0; ii < 2; ii++)
        #pragma unroll
        for (int jj = 0; jj < 2; jj++) {
            int m = m0 + ty * 2 + ii, n = n0 + tx * 2 + jj;
            float v = e[ii][jj] * scale;
            if (r1a)
                v += r1a[(size_t)bz * s1a + m] * r1b[(size_t)bz * s1b + n]
                   + r2a[(size_t)bz * s2a + m] * r2b[(size_t)bz * s2b + n];
            C[(size_t)m * N + n] = v;
        }
}

// ---------------- 64x64-tile batched GEMM (proven R7/R9) -----------------------
#define CPAD 68
#define CBUF (32 * CPAD)
__global__ __launch_bounds__(256) void k_mm64(
    const float* __restrict__ A, long long sA, int lda,
    const float* __restrict__ B, long long sB, int ldb,
    float* __restrict__ C, long long sC, int N, int K, float scale)
{
    __shared__ __align__(16) float As[2 * CBUF], Bs[2 * CBUF];
    int m0 = blockIdx.x * 64, n0 = blockIdx.y * 64, bz = blockIdx.z;
    A += (size_t)bz * sA; B += (size_t)bz * sB; C += (size_t)bz * sC;
    int tid = threadIdx.x;
    int lane = tid & 31, warp = tid >> 5;
    int rbase = warp * 8 + (lane >> 4) * 4;
    int cbase = (lane & 15) * 4;
    int ar = tid & 63, akg = tid >> 6;
    u64 acc[4][2] = {};
    float4 va[2], vb[2];

    #define CM_LOAD(t) do { \
        int kb = (t) * 32; \
        _Pragma("unroll") for (int l = 0; l < 2; l++) \
            va[l] = *(const float4*)&A[(size_t)(m0 + ar) * lda + kb + akg * 4 + l * 16]; \
        _Pragma("unroll") for (int l = 0; l < 2; l++) { \
            int e = tid + l * 256; \
            vb[l] = *(const float4*)&B[(size_t)(kb + (e >> 4)) * ldb + n0 + (e & 15) * 4]; \
        } \
    } while (0)

    #define CM_STORE(buf) do { \
        _Pragma("unroll") for (int l = 0; l < 2; l++) { \
            float tv[4]; *(float4*)tv = va[l]; \
            _Pragma("unroll") for (int q = 0; q < 4; q++) \
                As[(buf) * CBUF + (akg * 4 + l * 16 + q) * CPAD + ar] = tv[q]; \
        } \
        _Pragma("unroll") for (int l = 0; l < 2; l++) { \
            int e = tid + l * 256; \
            *(float4*)&Bs[(buf) * CBUF + (e >> 4) * CPAD + (e & 15) * 4] = vb[l]; \
        } \
    } while (0)

    const int T = K / 32;
    CM_LOAD(0);
    CM_STORE(0);
    if (T > 1) CM_LOAD(1);
    __syncthreads();
    #pragma unroll 1
    for (int t = 0; t < T; t++) {
        const float* Ab = &As[(t & 1) * CBUF];
        const float* Bb2 = &Bs[(t & 1) * CBUF];
        #pragma unroll 8
        for (int k = 0; k < 32; k++) {
            float4 a = *(const float4*)&Ab[k * CPAD + rbase];
            ulonglong2 bv = *(const ulonglong2*)&Bb2[k * CPAD + cbase];
            float av[4] = {a.x, a.y, a.z, a.w};
            #pragma unroll
            for (int i = 0; i < 4; i++) {
                u64 ad = pack2(av[i], av[i]);
                acc[i][0] = fma2(ad, bv.x, acc[i][0]);
                acc[i][1] = fma2(ad, bv.y, acc[i][1]);
            }
        }
        if (t + 1 < T) CM_STORE((t + 1) & 1);
        __syncthreads();
        if (t + 2 < T) CM_LOAD(t + 2);
    }
    #undef CM_LOAD
    #undef CM_STORE

    #pragma unroll
    for (int i = 0; i < 4; i++) {
        int m = m0 + rbase + i;
        float2 p0 = unpack2(acc[i][0]), p1 = unpack2(acc[i][1]);
        float4 v = make_float4(p0.x * scale, p0.y * scale, p1.x * scale, p1.y * scale);
        *(float4*)&C[(size_t)m * N + n0 + cbase] = v;
    }
}

// ---------------- fold theta_b + BN into per-(b,c) bias & alpha ----------------
__global__ __launch_bounds__(256) void k_dvec(
    const float* __restrict__ theta_b, const float* __restrict__ gamma,
    const float* __restrict__ beta, const float* __restrict__ mean,
    const float* __restrict__ var)
{
    int b = blockIdx.x, c = threadIdx.x;
    const float* Trow = g_T + ((size_t)b * Cc + c) * Cii;
    float d = 0.f;
    for (int i = 0; i < Cii; i++) d += Trow[i] * theta_b[i];
    float al = gamma[c] * rsqrtf(var[c] + 1e-5f);
    g_dp[b * Cc + c] = al * (d - mean[c]) + beta[c];
    if (b == 0) g_alpha[c] = al;
}

// ---------------- final: out[b] = alpha .* (Q[b] @ A[b]) + dp ------------------
// grid (2, 32, Bz); 128(c) x 128(n) tiles; Q coalesced+transposed, A natural.
__global__ __launch_bounds__(256, 2) void k_out(const float* __restrict__ aimg,
                                                float* __restrict__ out)
{
    extern __shared__ __align__(16) float sm[];
    float* Qs  = sm;                // 2 * TBUF
    float* Asn = sm + 2 * TBUF;     // 2 * TBUF
    int tc = blockIdx.x * 128;
    int tn = blockIdx.y * 128;
    int bz = blockIdx.z;
    const float* Ab = aimg + (size_t)bz * Cc * Nn;
    const float* Qb = g_Q + (size_t)bz * Cc * Cc;
    int tid = threadIdx.x;
    int lane = tid & 31, warp = tid >> 5;
    int rbase = warp * 16 + (lane >> 4) * 8;
    int cbase = (lane & 15) * 8;

    int er[4], ek[4], akr[4], anq[4];
    #pragma unroll
    for (int l = 0; l < 4; l++) {
        int e = tid + l * 256;
        er[l] = e >> 3; ek[l] = (e & 7) * 4;      // Q tile map
        akr[l] = e >> 5; anq[l] = (e & 31) * 4;   // A tile map
    }

    float4 vq[4], va[4];
    u64 acc[8][4] = {};

    #define FO_LOAD(t) do { \
        int kb = (t) * 32; \
        _Pragma("unroll") for (int l = 0; l < 4; l++) { \
            vq[l] = *(const float4*)&Qb[(size_t)(tc + er[l]) * Cc + kb + ek[l]]; \
            va[l] = *(const float4*)&Ab[(size_t)(kb + akr[l]) * Nn + tn + anq[l]]; \
        } \
    } while (0)

    #define FO_STORE(buf) do { \
        _Pragma("unroll") for (int l = 0; l < 4; l++) { \
            float tv[4]; *(float4*)tv = vq[l]; \
            _Pragma("unroll") for (int q = 0; q < 4; q++) \
                Qs[(buf) * TBUF + (ek[l] + q) * PAD + er[l]] = tv[q]; \
            *(float4*)&Asn[(buf) * TBUF + akr[l] * PAD + anq[l]] = va[l]; \
        } \
    } while (0)

    const int T = Cc / 32;   // 8
    FO_LOAD(0);
    FO_STORE(0);
    FO_LOAD(1);
    __syncthreads();
    #pragma unroll 1
    for (int t = 0; t < T; t++) {
        mm128(&Qs[(t & 1) * TBUF], &Asn[(t & 1) * TBUF], rbase, cbase, acc);
        if (t + 1 < T) FO_STORE((t + 1) & 1);
        __syncthreads();
        if (t + 2 < T) FO_LOAD(t + 2);
    }
    #undef FO_LOAD
    #undef FO_STORE

    float* outb = out + (size_t)bz * Cc * Nn;
    #pragma unroll
    for (int i = 0; i < 8; i++) {
        int c = tc + rbase + i;
        float al = g_alpha[c];
        float dpv = g_dp[bz * Cc + c];
        float2 p0 = unpack2(acc[i][0]), p1 = unpack2(acc[i][1]);
        float2 p2 = unpack2(acc[i][2]), p3 = unpack2(acc[i][3]);
        float* dst = &outb[(size_t)c * Nn + tn + cbase];
        *(float4*)dst = make_float4(al * p0.x + dpv, al * p0.y + dpv,
                                    al * p1.x + dpv, al * p1.y + dpv);
        *(float4*)(dst + 4) = make_float4(al * p2.x + dpv, al * p2.y + dpv,
                                          al * p3.x + dpv, al * p3.y + dpv);
    }
}

// -----------------------------------------------------------------------------
extern "C" void kernel_launch(void* const* d_in, const int* in_sizes, int n_in,
                              void* d_out, int out_size) {
    (void)in_sizes; (void)n_in; (void)out_size;
    const float* a       = (const float*)d_in[0];
    const float* bimg    = (const float*)d_in[1];
    const float* theta_w = (const float*)d_in[2];
    const float* theta_b = (const float*)d_in[3];
    const float* phi_w   = (const float*)d_in[4];
    const float* phi_b   = (const float*)d_in[5];
    const float* g_wp    = (const float*)d_in[6];
    const float* g_bp    = (const float*)d_in[7];
    const float* W_wp    = (const float*)d_in[8];
    const float* gamma   = (const float*)d_in[9];
    const float* beta    = (const float*)d_in[10];
    const float* mean    = (const float*)d_in[11];
    const float* var     = (const float*)d_in[12];

    static int attr_done = 0;
    if (!attr_done) {
        cudaFuncSetAttribute(k_syrk, cudaFuncAttributeMaxDynamicSharedMemorySize, SMEM_BIG);
        cudaFuncSetAttribute(k_out,  cudaFuncAttributeMaxDynamicSharedMemorySize, SMEM_BIG);
        attr_done = 1;
    }

    float *pR, *pU, *pS, *pT, *pQ, *pGs, *pPs2;
    cudaGetSymbolAddress((void**)&pR,   g_R);
    cudaGetSymbolAddress((void**)&pU,   g_U);
    cudaGetSymbolAddress((void**)&pS,   g_S);
    cudaGetSymbolAddress((void**)&pT,   g_T);
    cudaGetSymbolAddress((void**)&pQ,   g_Q);
    cudaGetSymbolAddress((void**)&pGs,  g_gs);
    cudaGetSymbolAddress((void**)&pPs2, g_ps2);

    k_zero<<<(Bz * Cc * Cc / 4) / 256, 256>>>();
    k_syrk<<<dim3(2, 2, Bz * KSsplit), 256, SMEM_BIG>>>(bimg);
    k_gsps<<<Bz, 256>>>(g_wp, phi_w, phi_b);

    // U[b] = g_w @ R[b]      [128,256], K=256
    k_mm64<<<dim3(Cii / 64, Cc / 64, Bz), 256>>>(
        g_wp, 0, Cc, pR, (long long)Cc * Cc, Cc,
        pU, (long long)Cii * Cc, Cc, Cc, 1.f);
    // S[b] = U[b] @ phi_w^T + gs*phib^T + gb*ps2^T   [128,128], K=256 (needs BT)
    k_gemm32<<<dim3(Cii / 32, Cii / 32, Bz), 256>>>(
        pU, (long long)Cii * Cc, phi_w, 0, pS, (long long)Cii * Cii,
        Cii, Cii, Cc, 1, 1.f,
        pGs, Cii, phi_b, 0, g_bp, 0, pPs2, Cii);
    // T[b] = W_w @ S[b] / N   [256,128], K=128
    k_mm64<<<dim3(Cc / 64, Cii / 64, Bz), 256>>>(
        W_wp, 0, Cii, pS, (long long)Cii * Cii, Cii,
        pT, (long long)Cc * Cii, Cii, Cii, 1.f / (float)Nn);
    // Q[b] = T[b] @ theta_w   [256,256], K=128
    k_mm64<<<dim3(Cc / 64, Cc / 64, Bz), 256>>>(
        pT, (long long)Cc * Cii, Cii, theta_w, 0, Cc,
        pQ, (long long)Cc * Cc, Cc, Cii, 1.f);

    k_dvec<<<Bz, 256>>>(theta_b, gamma, beta, mean, var);
    k_out<<<dim3(2, 32, Bz), 256, SMEM_BIG>>>(a, (float*)d_out);
}